// round 5
// baseline (speedup 1.0000x reference)
#include <cuda_runtime.h>
#include <math.h>

// ---------------------------------------------------------------------------
// SoftMoE forward, fp32, double-buffered cp.async SGEMM (128x128 / 64x128
// tiles, 8x8 microtiles).
// B=4, M=1024, D=768, E=16, P=64, F=3072.
// ---------------------------------------------------------------------------

namespace cfg {
constexpr int cB = 4, cM = 1024, cD = 768, cE = 16, cP = 64, cF = 3072;
constexpr int cEP = cE * cP;  // 1024
constexpr long long SZ_OUT  = (long long)cB * cM * cD;       // 3,145,728
constexpr long long SZ_PROB = (long long)cB * cM * cE;       //    65,536
constexpr long long SZ_TOP  = (long long)cB * cM;            //     4,096
constexpr long long SZ_HID  = (long long)cB * cE * cP * cF;  // 12,582,912
constexpr long long SZ_FULL = SZ_OUT + SZ_PROB + SZ_TOP + SZ_HID;
}
using namespace cfg;

// Scratch (allocation-free: __device__ globals).
__device__ float g_logits  [(size_t)cB * cM * cEP];
__device__ float g_dispatch[(size_t)cB * cM * cEP];
__device__ float g_combine [(size_t)cB * cM * cEP];
__device__ float g_mix     [(size_t)cB * cE * cP * cD];
__device__ float g_eout    [(size_t)cB * cE * cP * cD];
__device__ float g_hid_fb  [(size_t)cB * cE * cP * cF];

// ---------------------------------------------------------------------------
// cp.async helpers
// ---------------------------------------------------------------------------
__device__ __forceinline__ void cp_async16(void* s, const void* g) {
    unsigned sa = (unsigned)__cvta_generic_to_shared(s);
    asm volatile("cp.async.ca.shared.global [%0], [%1], 16;\n" :: "r"(sa), "l"(g));
}
__device__ __forceinline__ void cp_async4(void* s, const void* g) {
    unsigned sa = (unsigned)__cvta_generic_to_shared(s);
    asm volatile("cp.async.ca.shared.global [%0], [%1], 4;\n" :: "r"(sa), "l"(g));
}
__device__ __forceinline__ void cp_commit() {
    asm volatile("cp.async.commit_group;\n");
}
template <int N>
__device__ __forceinline__ void cp_wait() {
    asm volatile("cp.async.wait_group %0;\n" :: "n"(N));
}

__device__ __forceinline__ float gelu_tanh(float x) {
    float x3 = x * x * x;
    return 0.5f * x * (1.0f + tanhf(0.7978845608028654f * (x + 0.044715f * x3)));
}

// ---------------------------------------------------------------------------
// Tiled SGEMM: C[M,N] = op(A)[M,K] * B[K,N] (+bias[N]) (+gelu)
//   TM in {64,128}, TN=128, TK=16. 256 threads, microtile (TM/16) x 8.
// op(A)=A   row-major [Md,Kd]          when !TRANSA
// op(A)=A^T with A row-major [Kd,Md]   when TRANSA
// Batched over blockIdx.z: A += z*sA, B += (z%bmod)*sB, C += z*sC,
//                          bias += (z%bmod)*sBias.
// Requires: Md % TM == 0, Nd % 128 == 0, Kd % 16 == 0.
// ---------------------------------------------------------------------------
#define TBN 128
#define TBK 16

template <int TM, bool TRANSA, int ACT>
__global__ __launch_bounds__(256) void gemm_db(
    const float* __restrict__ A, const float* __restrict__ B,
    float* __restrict__ C, const float* __restrict__ bias,
    int Md, int Nd, int Kd,
    long long sA, long long sB, long long sC,
    int bmod, long long sBias)
{
    constexpr int MT = TM / 16;  // rows per thread (8 or 4)

    const int z = blockIdx.z;
    A += (long long)z * sA;
    B += (long long)(z % bmod) * sB;
    C += (long long)z * sC;
    if (bias) bias += (long long)(z % bmod) * sBias;

    __shared__ float As[2][TBK][TM + 4];
    __shared__ float Bs[2][TBK][TBN + 4];

    const int tid = threadIdx.x;
    const int tx = tid & 15;   // 0..15 -> 8 output cols each
    const int ty = tid >> 4;   // 0..15 -> MT output rows each
    const int row0 = blockIdx.y * TM;
    const int col0 = blockIdx.x * TBN;

    auto loadA = [&](int buf, int k0) {
        if (!TRANSA) {
            // A row-major [Md,Kd]; contiguous along k. Scalar cp.async.
            constexpr int TOT = TM * TBK;
            #pragma unroll
            for (int i = 0; i < TOT / 256; i++) {
                int l = tid + i * 256;
                int kk = l & 15, mm = l >> 4;
                cp_async4(&As[buf][kk][mm],
                          &A[(long long)(row0 + mm) * Kd + (k0 + kk)]);
            }
        } else {
            // A row-major [Kd,Md]; contiguous along m. Vector cp.async.
            constexpr int TOT = TM * TBK;  // floats
            #pragma unroll
            for (int i = 0; i < TOT / 1024; i++) {
                int l = tid * 4 + i * 1024;
                int ii = l % TM, kk = l / TM;
                cp_async16(&As[buf][kk][ii],
                           &A[(long long)(k0 + kk) * Md + (row0 + ii)]);
            }
        }
    };
    auto loadB = [&](int buf, int k0) {
        #pragma unroll
        for (int i = 0; i < (TBN * TBK) / 1024; i++) {
            int l = tid * 4 + i * 1024;
            int nn = l % TBN, kk = l / TBN;
            cp_async16(&Bs[buf][kk][nn],
                       &B[(long long)(k0 + kk) * Nd + (col0 + nn)]);
        }
    };

    float acc[MT][8] = {};

    loadA(0, 0);
    loadB(0, 0);
    cp_commit();

    const int nk = Kd / TBK;
    int buf = 0;
    for (int it = 0; it < nk; it++) {
        if (it + 1 < nk) {
            loadA(buf ^ 1, (it + 1) * TBK);
            loadB(buf ^ 1, (it + 1) * TBK);
            cp_commit();
            cp_wait<1>();
        } else {
            cp_wait<0>();
        }
        __syncthreads();

        #pragma unroll
        for (int kk = 0; kk < TBK; kk++) {
            float a[MT], b[8];
            #pragma unroll
            for (int q = 0; q < MT / 4; q++) {
                float4 a4 = *reinterpret_cast<const float4*>(&As[buf][kk][ty * MT + 4 * q]);
                a[4 * q + 0] = a4.x; a[4 * q + 1] = a4.y;
                a[4 * q + 2] = a4.z; a[4 * q + 3] = a4.w;
            }
            float4 b0 = *reinterpret_cast<const float4*>(&Bs[buf][kk][tx * 8]);
            float4 b1 = *reinterpret_cast<const float4*>(&Bs[buf][kk][tx * 8 + 4]);
            b[0] = b0.x; b[1] = b0.y; b[2] = b0.z; b[3] = b0.w;
            b[4] = b1.x; b[5] = b1.y; b[6] = b1.z; b[7] = b1.w;
            #pragma unroll
            for (int i = 0; i < MT; i++)
                #pragma unroll
                for (int j = 0; j < 8; j++)
                    acc[i][j] = fmaf(a[i], b[j], acc[i][j]);
        }
        __syncthreads();
        buf ^= 1;
    }

    // Epilogue
    float bv[8];
    if (bias) {
        #pragma unroll
        for (int j = 0; j < 8; j++) bv[j] = bias[col0 + tx * 8 + j];
    }
    #pragma unroll
    for (int i = 0; i < MT; i++) {
        int r = row0 + ty * MT + i;
        float v[8];
        #pragma unroll
        for (int j = 0; j < 8; j++) {
            float t = acc[i][j];
            if (bias) t += bv[j];
            if (ACT == 1) t = gelu_tanh(t);
            v[j] = t;
        }
        float4* cp = reinterpret_cast<float4*>(&C[(long long)r * Nd + col0 + tx * 8]);
        cp[0] = make_float4(v[0], v[1], v[2], v[3]);
        cp[1] = make_float4(v[4], v[5], v[6], v[7]);
    }
}

// ---------------------------------------------------------------------------
// dispatch = softmax over tokens m (axis 1).
// ---------------------------------------------------------------------------
__global__ __launch_bounds__(256) void dispatch_softmax_kernel(
    const float* __restrict__ logits, float* __restrict__ dispatch)
{
    const int b = blockIdx.y;
    const int ep = blockIdx.x * 32 + threadIdx.x;
    const int tx = threadIdx.x, ty = threadIdx.y;
    const float* base = logits + (long long)b * cM * cEP + ep;
    float* obase = dispatch + (long long)b * cM * cEP + ep;

    float mx = -INFINITY, s = 0.0f;
    for (int m = ty; m < cM; m += 8) {
        float v = base[(long long)m * cEP];
        float nm = fmaxf(mx, v);
        s = s * expf(mx - nm) + expf(v - nm);
        mx = nm;
    }
    __shared__ float smx[8][32], ssum[8][32];
    smx[ty][tx] = mx;
    ssum[ty][tx] = s;
    __syncthreads();
    if (ty == 0) {
        float M_ = smx[0][tx], S = ssum[0][tx];
        #pragma unroll
        for (int i = 1; i < 8; i++) {
            float m2 = smx[i][tx];
            float nm = fmaxf(M_, m2);
            S = S * expf(M_ - nm) + ssum[i][tx] * expf(m2 - nm);
            M_ = nm;
        }
        smx[0][tx] = M_;
        ssum[0][tx] = 1.0f / S;
    }
    __syncthreads();
    const float gmx = smx[0][tx];
    const float inv = ssum[0][tx];
    for (int m = ty; m < cM; m += 8)
        obase[(long long)m * cEP] = expf(base[(long long)m * cEP] - gmx) * inv;
}

// ---------------------------------------------------------------------------
// combine = softmax over ep + probabilities + argmax.
// ---------------------------------------------------------------------------
__global__ __launch_bounds__(256) void combine_softmax_kernel(
    const float* __restrict__ logits, float* __restrict__ combine,
    float* __restrict__ prob, float* __restrict__ top)
{
    const long long bm = blockIdx.y * gridDim.x + blockIdx.x;
    const float* row = logits + bm * cEP;
    float* crow = combine + bm * cEP;

    __shared__ float sv[cEP];
    __shared__ float sred[8];
    __shared__ float sbc;
    __shared__ float sprob[cE];

    const int tid = threadIdx.x;
    const int lane = tid & 31, warp = tid >> 5;

    float v[4];
    float mx = -INFINITY;
    #pragma unroll
    for (int i = 0; i < 4; i++) {
        v[i] = row[tid + i * 256];
        mx = fmaxf(mx, v[i]);
    }
    #pragma unroll
    for (int off = 16; off > 0; off >>= 1)
        mx = fmaxf(mx, __shfl_xor_sync(0xffffffffu, mx, off));
    if (lane == 0) sred[warp] = mx;
    __syncthreads();
    if (tid == 0) {
        float m = sred[0];
        #pragma unroll
        for (int i = 1; i < 8; i++) m = fmaxf(m, sred[i]);
        sbc = m;
    }
    __syncthreads();
    const float gmx = sbc;

    float s = 0.0f;
    #pragma unroll
    for (int i = 0; i < 4; i++) {
        float e = expf(v[i] - gmx);
        sv[tid + i * 256] = e;
        s += e;
    }
    #pragma unroll
    for (int off = 16; off > 0; off >>= 1)
        s += __shfl_xor_sync(0xffffffffu, s, off);
    if (lane == 0) sred[warp] = s;
    __syncthreads();
    if (tid == 0) {
        float t = 0.0f;
        #pragma unroll
        for (int i = 0; i < 8; i++) t += sred[i];
        sbc = 1.0f / t;
    }
    __syncthreads();
    const float inv = sbc;

    #pragma unroll
    for (int i = 0; i < 4; i++)
        crow[tid + i * 256] = sv[tid + i * 256] * inv;

    #pragma unroll
    for (int e = warp * 2; e < warp * 2 + 2; e++) {
        float s2 = sv[e * 64 + lane] + sv[e * 64 + 32 + lane];
        #pragma unroll
        for (int off = 16; off > 0; off >>= 1)
            s2 += __shfl_xor_sync(0xffffffffu, s2, off);
        if (lane == 0) sprob[e] = s2 * inv * (1.0f / 64.0f);
    }
    __syncthreads();
    if (prob && tid < cE) prob[bm * cE + tid] = sprob[tid];
    if (top && tid == 0) {
        float best = -INFINITY;
        int bi = 0;
        #pragma unroll
        for (int e = 0; e < cE; e++) {
            if (sprob[e] > best) { best = sprob[e]; bi = e; }
        }
        top[bm] = (float)bi;
    }
}

// ---------------------------------------------------------------------------
// Host-side launch
// ---------------------------------------------------------------------------
extern "C" void kernel_launch(void* const* d_in, const int* in_sizes, int n_in,
                              void* d_out, int out_size)
{
    const float* x   = (const float*)d_in[0];  // [B, M, D]
    const float* phi = (const float*)d_in[1];  // [D, EP]
    const float* W1  = (const float*)d_in[2];  // [E, D, F]
    const float* b1  = (const float*)d_in[3];  // [E, F]
    const float* W2  = (const float*)d_in[4];  // [E, F, D]
    const float* b2  = (const float*)d_in[5];  // [E, D]
    float* out = (float*)d_out;

    float *logits, *dispatchp, *combinep, *mixp, *eoutp, *hidfb;
    cudaGetSymbolAddress((void**)&logits,    g_logits);
    cudaGetSymbolAddress((void**)&dispatchp, g_dispatch);
    cudaGetSymbolAddress((void**)&combinep,  g_combine);
    cudaGetSymbolAddress((void**)&mixp,      g_mix);
    cudaGetSymbolAddress((void**)&eoutp,     g_eout);
    cudaGetSymbolAddress((void**)&hidfb,     g_hid_fb);

    const bool full = ((long long)out_size >= SZ_FULL);
    float* hidp  = full ? (out + SZ_OUT + SZ_PROB + SZ_TOP) : hidfb;
    float* probp = full ? (out + SZ_OUT) : nullptr;
    float* topp  = full ? (out + SZ_OUT + SZ_PROB) : nullptr;

    // 1) logits = X[4096,768] @ phi[768,1024]
    {
        dim3 grid(cEP / TBN, (cB * cM) / 128, 1);
        gemm_db<128, false, 0><<<grid, 256>>>(x, phi, logits, nullptr,
            cB * cM, cEP, cD, 0, 0, 0, 1, 0);
    }

    // 2) dispatch = softmax over tokens
    dispatch_softmax_kernel<<<dim3(cEP / 32, cB), dim3(32, 8)>>>(logits, dispatchp);

    // 3) combine = softmax over (e,p) + probabilities + argmax
    combine_softmax_kernel<<<dim3(cM, cB), 256>>>(logits, combinep, probp, topp);

    // 4) mix[b,ep,d] = dispatch[b]^T @ X[b]
    {
        dim3 grid(cD / TBN, cEP / 128, cB);
        gemm_db<128, true, 0><<<grid, 256>>>(dispatchp, x, mixp, nullptr,
            cEP, cD, cM,
            (long long)cM * cEP, (long long)cM * cD, (long long)cEP * cD,
            cB, 0);
    }

    // 5) hidden = gelu(mix @ W1 + b1)  per (b,e) group (M=64)
    {
        dim3 grid(cF / TBN, cP / 64, cB * cE);
        gemm_db<64, false, 1><<<grid, 256>>>(mixp, W1, hidp, b1,
            cP, cF, cD,
            (long long)cP * cD, (long long)cD * cF, (long long)cP * cF,
            cE, cF);
    }

    // 6) eout = hidden @ W2 + b2  per (b,e) group (M=64)
    {
        dim3 grid(cD / TBN, cP / 64, cB * cE);
        gemm_db<64, false, 0><<<grid, 256>>>(hidp, W2, eoutp, b2,
            cP, cD, cF,
            (long long)cP * cF, (long long)cF * cD, (long long)cP * cD,
            cE, cD);
    }

    // 7) outputs = combine[b] @ eout[b]
    {
        dim3 grid(cD / TBN, cM / 128, cB);
        gemm_db<128, false, 0><<<grid, 256>>>(combinep, eoutp, out, nullptr,
            cM, cD, cEP,
            (long long)cM * cEP, (long long)cEP * cD, (long long)cM * cD,
            cB, 0);
    }
}

// round 6
// speedup vs baseline: 2.4727x; 2.4727x over previous
#include <cuda_runtime.h>
#include <math.h>
#include <stdint.h>

// ---------------------------------------------------------------------------
// SoftMoE forward. GEMMs on tensor cores (mma.sync m16n8k8 tf32, fp32 accum).
// logits GEMM uses 3xTF32 error compensation (fp32-grade) to keep the
// probabilities/argmax outputs stable; all other GEMMs are single-pass tf32.
// B=4, M=1024, D=768, E=16, P=64, F=3072.
// ---------------------------------------------------------------------------

namespace cfg {
constexpr int cB = 4, cM = 1024, cD = 768, cE = 16, cP = 64, cF = 3072;
constexpr int cEP = cE * cP;  // 1024
constexpr long long SZ_OUT  = (long long)cB * cM * cD;
constexpr long long SZ_PROB = (long long)cB * cM * cE;
constexpr long long SZ_TOP  = (long long)cB * cM;
constexpr long long SZ_HID  = (long long)cB * cE * cP * cF;
constexpr long long SZ_FULL = SZ_OUT + SZ_PROB + SZ_TOP + SZ_HID;
}
using namespace cfg;

// Scratch (allocation-free: __device__ globals).
__device__ float g_logits  [(size_t)cB * cM * cEP];
__device__ float g_dispatch[(size_t)cB * cM * cEP];
__device__ float g_combine [(size_t)cB * cM * cEP];
__device__ float g_mix     [(size_t)cB * cE * cP * cD];
__device__ float g_eout    [(size_t)cB * cE * cP * cD];
__device__ float g_hid_fb  [(size_t)cB * cE * cP * cF];

// ---------------------------------------------------------------------------
// PTX helpers
// ---------------------------------------------------------------------------
__device__ __forceinline__ void cp_async16(void* s, const void* g) {
    unsigned sa = (unsigned)__cvta_generic_to_shared(s);
    asm volatile("cp.async.ca.shared.global [%0], [%1], 16;\n" :: "r"(sa), "l"(g));
}
__device__ __forceinline__ void cp_async4(void* s, const void* g) {
    unsigned sa = (unsigned)__cvta_generic_to_shared(s);
    asm volatile("cp.async.ca.shared.global [%0], [%1], 4;\n" :: "r"(sa), "l"(g));
}
__device__ __forceinline__ void cp_commit() {
    asm volatile("cp.async.commit_group;\n");
}
template <int N>
__device__ __forceinline__ void cp_wait() {
    asm volatile("cp.async.wait_group %0;\n" :: "n"(N));
}

__device__ __forceinline__ uint32_t f2tf(float x) {
    uint32_t u;
    asm("cvt.rna.tf32.f32 %0, %1;" : "=r"(u) : "f"(x));
    return u;
}

__device__ __forceinline__ void mma_tf32(float c[4], const uint32_t a[4],
                                         const uint32_t b[2]) {
    asm volatile(
        "mma.sync.aligned.m16n8k8.row.col.f32.tf32.tf32.f32 "
        "{%0,%1,%2,%3}, {%4,%5,%6,%7}, {%8,%9}, {%0,%1,%2,%3};\n"
        : "+f"(c[0]), "+f"(c[1]), "+f"(c[2]), "+f"(c[3])
        : "r"(a[0]), "r"(a[1]), "r"(a[2]), "r"(a[3]),
          "r"(b[0]), "r"(b[1]));
}

__device__ __forceinline__ float gelu_tanh(float x) {
    float x3 = x * x * x;
    return 0.5f * x * (1.0f + tanhf(0.7978845608028654f * (x + 0.044715f * x3)));
}

// ---------------------------------------------------------------------------
// Tensor-core GEMM: C[Md,Nd] = op(A)[Md,Kd] * B[Kd,Nd] (+bias[Nd]) (+gelu)
//   TM in {64,128}, TN=128, TK=16. 256 threads = 8 warps (2 along M, 4 along N).
//   Warp tile (TM/2) x 32, built from m16n8k8 tf32 mmas.
// op(A)=A   row-major [Md,Kd]          when !TRANSA
// op(A)=A^T with A row-major [Kd,Md]   when TRANSA (Md is the row stride)
// SPLIT: 3xTF32 error-compensated pass (fp32-grade accuracy).
// Batched over blockIdx.z: r = z % zdiv, g = z / zdiv;
//   A += r*sA_r + g*sA_g; B += g*sB_g; C += r*sC_r + g*sC_g; bias += g*sBias_g.
// Requires: Md % TM == 0, Nd % 128 == 0, Kd % 16 == 0.
// ---------------------------------------------------------------------------
#define TBN 128
#define TBK 16

template <int TM, bool TRANSA, int ACT, bool SPLIT>
__global__ __launch_bounds__(256) void gemm_tc(
    const float* __restrict__ A, const float* __restrict__ B,
    float* __restrict__ C, const float* __restrict__ bias,
    int Md, int Nd, int Kd,
    long long sA_r, long long sA_g, long long sB_g,
    long long sC_r, long long sC_g, long long sBias_g,
    int zdiv)
{
    constexpr int SAS = TM + 8;    // As row stride (floats): 72 or 136
    constexpr int SBS = TBN + 8;   // Bs row stride: 136
    constexpr int WM = TM / 2;     // warp M extent
    constexpr int MI = WM / 16;    // m16 tiles per warp (2 or 4)
    constexpr int NI = 4;          // n8 tiles per warp (32 cols)

    const int z = blockIdx.z;
    const int rb = z % zdiv, gg = z / zdiv;
    A += (long long)rb * sA_r + (long long)gg * sA_g;
    B += (long long)gg * sB_g;
    C += (long long)rb * sC_r + (long long)gg * sC_g;
    if (bias) bias += (long long)gg * sBias_g;

    __shared__ float As[2][TBK][SAS];
    __shared__ float Bs[2][TBK][SBS];

    const int tid  = threadIdx.x;
    const int lane = tid & 31, warp = tid >> 5;
    const int t  = lane & 3;       // threadID in quad (k / col selector)
    const int gq = lane >> 2;      // group id (row selector)
    const int wm = warp & 1, wn = warp >> 1;
    const int m_base = wm * WM;
    const int n_base = wn * 32;
    const int row0 = blockIdx.y * TM;
    const int col0 = blockIdx.x * TBN;

    auto loadA = [&](int buf, int k0) {
        if (!TRANSA) {
            constexpr int TOT = TM * TBK;
            #pragma unroll
            for (int i = 0; i < TOT / 256; i++) {
                int l = tid + i * 256;
                int kk = l & 15, mm = l >> 4;
                cp_async4(&As[buf][kk][mm],
                          &A[(long long)(row0 + mm) * Kd + (k0 + kk)]);
            }
        } else {
            constexpr int TOT = TM * TBK;
            #pragma unroll
            for (int i = 0; i < TOT / 1024; i++) {
                int l = tid * 4 + i * 1024;
                int ii = l % TM, kk = l / TM;
                cp_async16(&As[buf][kk][ii],
                           &A[(long long)(k0 + kk) * Md + (row0 + ii)]);
            }
        }
    };
    auto loadB = [&](int buf, int k0) {
        #pragma unroll
        for (int i = 0; i < (TBN * TBK) / 1024; i++) {
            int l = tid * 4 + i * 1024;
            int nn = l % TBN, kk = l / TBN;
            cp_async16(&Bs[buf][kk][nn],
                       &B[(long long)(k0 + kk) * Nd + (col0 + nn)]);
        }
    };

    float acc[MI][NI][4];
    #pragma unroll
    for (int i = 0; i < MI; i++)
        #pragma unroll
        for (int j = 0; j < NI; j++)
            #pragma unroll
            for (int q = 0; q < 4; q++) acc[i][j][q] = 0.0f;

    loadA(0, 0);
    loadB(0, 0);
    cp_commit();

    const int nk = Kd / TBK;
    int buf = 0;
    for (int it = 0; it < nk; it++) {
        if (it + 1 < nk) {
            loadA(buf ^ 1, (it + 1) * TBK);
            loadB(buf ^ 1, (it + 1) * TBK);
            cp_commit();
            cp_wait<1>();
        } else {
            cp_wait<0>();
        }
        __syncthreads();

        #pragma unroll
        for (int ks = 0; ks < TBK; ks += 8) {
            uint32_t Ah[MI][4], Bh[NI][2];
            uint32_t Al[MI][4], Bl[NI][2];

            #pragma unroll
            for (int mi = 0; mi < MI; mi++) {
                const int m0 = m_base + mi * 16;
                float v[4];
                v[0] = As[buf][ks + t    ][m0 + gq];
                v[1] = As[buf][ks + t    ][m0 + gq + 8];
                v[2] = As[buf][ks + t + 4][m0 + gq];
                v[3] = As[buf][ks + t + 4][m0 + gq + 8];
                #pragma unroll
                for (int q = 0; q < 4; q++) {
                    Ah[mi][q] = f2tf(v[q]);
                    if (SPLIT)
                        Al[mi][q] = f2tf(v[q] - __uint_as_float(Ah[mi][q]));
                }
            }
            #pragma unroll
            for (int ni = 0; ni < NI; ni++) {
                const int n0 = n_base + ni * 8;
                float u0 = Bs[buf][ks + t    ][n0 + gq];
                float u1 = Bs[buf][ks + t + 4][n0 + gq];
                Bh[ni][0] = f2tf(u0);
                Bh[ni][1] = f2tf(u1);
                if (SPLIT) {
                    Bl[ni][0] = f2tf(u0 - __uint_as_float(Bh[ni][0]));
                    Bl[ni][1] = f2tf(u1 - __uint_as_float(Bh[ni][1]));
                }
            }

            #pragma unroll
            for (int mi = 0; mi < MI; mi++)
                #pragma unroll
                for (int ni = 0; ni < NI; ni++) {
                    if (SPLIT) {
                        mma_tf32(acc[mi][ni], Ah[mi], Bl[ni]);
                        mma_tf32(acc[mi][ni], Al[mi], Bh[ni]);
                    }
                    mma_tf32(acc[mi][ni], Ah[mi], Bh[ni]);
                }
        }
        __syncthreads();
        buf ^= 1;
    }

    // Epilogue: c0,c1 at (row, 2t/2t+1); c2,c3 at (row+8, same cols)
    #pragma unroll
    for (int mi = 0; mi < MI; mi++) {
        const int r1 = row0 + m_base + mi * 16 + gq;
        #pragma unroll
        for (int ni = 0; ni < NI; ni++) {
            const int cg = col0 + n_base + ni * 8 + 2 * t;
            float b0 = 0.0f, b1 = 0.0f;
            if (bias) { b0 = bias[cg]; b1 = bias[cg + 1]; }
            float v0 = acc[mi][ni][0] + b0;
            float v1 = acc[mi][ni][1] + b1;
            float v2 = acc[mi][ni][2] + b0;
            float v3 = acc[mi][ni][3] + b1;
            if (ACT == 1) {
                v0 = gelu_tanh(v0); v1 = gelu_tanh(v1);
                v2 = gelu_tanh(v2); v3 = gelu_tanh(v3);
            }
            *reinterpret_cast<float2*>(&C[(long long)r1 * Nd + cg]) =
                make_float2(v0, v1);
            *reinterpret_cast<float2*>(&C[(long long)(r1 + 8) * Nd + cg]) =
                make_float2(v2, v3);
        }
    }
}

// ---------------------------------------------------------------------------
// dispatch = softmax over tokens m (axis 1).
// ---------------------------------------------------------------------------
__global__ __launch_bounds__(256) void dispatch_softmax_kernel(
    const float* __restrict__ logits, float* __restrict__ dispatch)
{
    const int b = blockIdx.y;
    const int ep = blockIdx.x * 32 + threadIdx.x;
    const int tx = threadIdx.x, ty = threadIdx.y;
    const float* base = logits + (long long)b * cM * cEP + ep;
    float* obase = dispatch + (long long)b * cM * cEP + ep;

    float mx = -INFINITY, s = 0.0f;
    for (int m = ty; m < cM; m += 8) {
        float v = base[(long long)m * cEP];
        float nm = fmaxf(mx, v);
        s = s * expf(mx - nm) + expf(v - nm);
        mx = nm;
    }
    __shared__ float smx[8][32], ssum[8][32];
    smx[ty][tx] = mx;
    ssum[ty][tx] = s;
    __syncthreads();
    if (ty == 0) {
        float M_ = smx[0][tx], S = ssum[0][tx];
        #pragma unroll
        for (int i = 1; i < 8; i++) {
            float m2 = smx[i][tx];
            float nm = fmaxf(M_, m2);
            S = S * expf(M_ - nm) + ssum[i][tx] * expf(m2 - nm);
            M_ = nm;
        }
        smx[0][tx] = M_;
        ssum[0][tx] = 1.0f / S;
    }
    __syncthreads();
    const float gmx = smx[0][tx];
    const float inv = ssum[0][tx];
    for (int m = ty; m < cM; m += 8)
        obase[(long long)m * cEP] = expf(base[(long long)m * cEP] - gmx) * inv;
}

// ---------------------------------------------------------------------------
// combine = softmax over ep + probabilities + argmax.
// ---------------------------------------------------------------------------
__global__ __launch_bounds__(256) void combine_softmax_kernel(
    const float* __restrict__ logits, float* __restrict__ combine,
    float* __restrict__ prob, float* __restrict__ top)
{
    const long long bm = blockIdx.y * gridDim.x + blockIdx.x;
    const float* row = logits + bm * cEP;
    float* crow = combine + bm * cEP;

    __shared__ float sv[cEP];
    __shared__ float sred[8];
    __shared__ float sbc;
    __shared__ float sprob[cE];

    const int tid = threadIdx.x;
    const int lane = tid & 31, warp = tid >> 5;

    float v[4];
    float mx = -INFINITY;
    #pragma unroll
    for (int i = 0; i < 4; i++) {
        v[i] = row[tid + i * 256];
        mx = fmaxf(mx, v[i]);
    }
    #pragma unroll
    for (int off = 16; off > 0; off >>= 1)
        mx = fmaxf(mx, __shfl_xor_sync(0xffffffffu, mx, off));
    if (lane == 0) sred[warp] = mx;
    __syncthreads();
    if (tid == 0) {
        float m = sred[0];
        #pragma unroll
        for (int i = 1; i < 8; i++) m = fmaxf(m, sred[i]);
        sbc = m;
    }
    __syncthreads();
    const float gmx = sbc;

    float s = 0.0f;
    #pragma unroll
    for (int i = 0; i < 4; i++) {
        float e = expf(v[i] - gmx);
        sv[tid + i * 256] = e;
        s += e;
    }
    #pragma unroll
    for (int off = 16; off > 0; off >>= 1)
        s += __shfl_xor_sync(0xffffffffu, s, off);
    if (lane == 0) sred[warp] = s;
    __syncthreads();
    if (tid == 0) {
        float tt = 0.0f;
        #pragma unroll
        for (int i = 0; i < 8; i++) tt += sred[i];
        sbc = 1.0f / tt;
    }
    __syncthreads();
    const float inv = sbc;

    #pragma unroll
    for (int i = 0; i < 4; i++)
        crow[tid + i * 256] = sv[tid + i * 256] * inv;

    #pragma unroll
    for (int e = warp * 2; e < warp * 2 + 2; e++) {
        float s2 = sv[e * 64 + lane] + sv[e * 64 + 32 + lane];
        #pragma unroll
        for (int off = 16; off > 0; off >>= 1)
            s2 += __shfl_xor_sync(0xffffffffu, s2, off);
        if (lane == 0) sprob[e] = s2 * inv * (1.0f / 64.0f);
    }
    __syncthreads();
    if (prob && tid < cE) prob[bm * cE + tid] = sprob[tid];
    if (top && tid == 0) {
        float best = -INFINITY;
        int bi = 0;
        #pragma unroll
        for (int e = 0; e < cE; e++) {
            if (sprob[e] > best) { best = sprob[e]; bi = e; }
        }
        top[bm] = (float)bi;
    }
}

// ---------------------------------------------------------------------------
// Host-side launch
// ---------------------------------------------------------------------------
extern "C" void kernel_launch(void* const* d_in, const int* in_sizes, int n_in,
                              void* d_out, int out_size)
{
    const float* x   = (const float*)d_in[0];  // [B, M, D]
    const float* phi = (const float*)d_in[1];  // [D, EP]
    const float* W1  = (const float*)d_in[2];  // [E, D, F]
    const float* b1  = (const float*)d_in[3];  // [E, F]
    const float* W2  = (const float*)d_in[4];  // [E, F, D]
    const float* b2  = (const float*)d_in[5];  // [E, D]
    float* out = (float*)d_out;

    float *logits, *dispatchp, *combinep, *mixp, *eoutp, *hidfb;
    cudaGetSymbolAddress((void**)&logits,    g_logits);
    cudaGetSymbolAddress((void**)&dispatchp, g_dispatch);
    cudaGetSymbolAddress((void**)&combinep,  g_combine);
    cudaGetSymbolAddress((void**)&mixp,      g_mix);
    cudaGetSymbolAddress((void**)&eoutp,     g_eout);
    cudaGetSymbolAddress((void**)&hidfb,     g_hid_fb);

    const bool full = ((long long)out_size >= SZ_FULL);
    float* hidp  = full ? (out + SZ_OUT + SZ_PROB + SZ_TOP) : hidfb;
    float* probp = full ? (out + SZ_OUT) : nullptr;
    float* topp  = full ? (out + SZ_OUT + SZ_PROB) : nullptr;

    // 1) logits = X[4096,768] @ phi[768,1024]  — 3xTF32 (fp32-grade; feeds
    //    softmaxes, probabilities and argmax)
    gemm_tc<128, false, 0, true><<<dim3(cEP / TBN, (cB * cM) / 128, 1), 256>>>(
        x, phi, logits, nullptr, cB * cM, cEP, cD,
        0, 0, 0, 0, 0, 0, 1);

    // 2) dispatch = softmax over tokens
    dispatch_softmax_kernel<<<dim3(cEP / 32, cB), dim3(32, 8)>>>(logits, dispatchp);

    // 3) combine = softmax over (e,p) + probabilities + argmax
    combine_softmax_kernel<<<dim3(cM, cB), 256>>>(logits, combinep, probp, topp);

    // 4) mix[b,ep,d] = dispatch[b]^T @ X[b]   (tf32)
    gemm_tc<128, true, 0, false><<<dim3(cD / TBN, cEP / 128, cB), 256>>>(
        dispatchp, x, mixp, nullptr, cEP, cD, cM,
        0, (long long)cM * cEP, (long long)cM * cD,
        0, (long long)cEP * cD, 0, 1);

    // 5) hidden = gelu(mix @ W1 + b1)  per (b,e); z = e*B+b for W-reuse in L2
    gemm_tc<64, false, 1, false><<<dim3(cF / TBN, 1, cB * cE), 256>>>(
        mixp, W1, hidp, b1, cP, cF, cD,
        (long long)cE * cP * cD, (long long)cP * cD, (long long)cD * cF,
        (long long)cE * cP * cF, (long long)cP * cF, (long long)cF, cB);

    // 6) eout = hidden @ W2 + b2  per (b,e)
    gemm_tc<64, false, 0, false><<<dim3(cD / TBN, 1, cB * cE), 256>>>(
        hidp, W2, eoutp, b2, cP, cD, cF,
        (long long)cE * cP * cF, (long long)cP * cF, (long long)cF * cD,
        (long long)cE * cP * cD, (long long)cP * cD, (long long)cD, cB);

    // 7) outputs = combine[b] @ eout[b]   (tf32)
    gemm_tc<128, false, 0, false><<<dim3(cD / TBN, cM / 128, cB), 256>>>(
        combinep, eoutp, out, nullptr, cM, cD, cEP,
        0, (long long)cM * cEP, (long long)cEP * cD,
        0, (long long)cM * cD, 0, 1);
}